// round 14
// baseline (speedup 1.0000x reference)
#include <cuda_runtime.h>
#include <cuda_fp16.h>
#include <cstdint>

// Shapes: x[256,100,512] f32, W1[1024,512] f32, b1[1024], W2[8,1024], b2[8]
// out[256,8] f32.
#define T_STEPS 100
#define B_SZ    256
#define IN_F    512
#define HID     1024
#define CLS     8
#define M_TOTAL (B_SZ * T_STEPS)   // 25600
#define KW      1024               // 2 fp16 terms x 512

// ---------------- device scratch (static; no allocations) -----------------
__device__ float  g_cur[(size_t)M_TOTAL * HID];   // 104.9 MB
__device__ __half g_A2[(size_t)M_TOTAL * KW];     // [m][a0|a1] 52.4 MB
__device__ __half g_B2[(size_t)HID * KW];         // [n][b0|b1]  2.1 MB

// ---------------- base-PTX helpers (sm_80+) --------------------------------
__device__ __forceinline__ uint32_t smem_u32(const void* p) {
    uint32_t a;
    asm("{ .reg .u64 t; cvta.to.shared.u64 t, %1; cvt.u32.u64 %0, t; }" : "=r"(a) : "l"(p));
    return a;
}
__device__ __forceinline__ void cp16(uint32_t dst, const void* src) {
    asm volatile("cp.async.cg.shared.global [%0], [%1], 16;" :: "r"(dst), "l"(src));
}
#define CP_COMMIT() asm volatile("cp.async.commit_group;")
#define CP_WAIT(n)  asm volatile("cp.async.wait_group %0;" :: "n"(n))

__device__ __forceinline__ void ldm_x4(uint32_t* r, uint32_t addr) {
    asm volatile("ldmatrix.sync.aligned.m8n8.x4.shared.b16 {%0,%1,%2,%3}, [%4];"
        : "=r"(r[0]), "=r"(r[1]), "=r"(r[2]), "=r"(r[3]) : "r"(addr));
}
// Chained mma: D += A*B through the TC accumulator (RZ-biased add; safe only
// while |acc| stays ~2^-11 -- phase-1 segments).
__device__ __forceinline__ void mma_chain(float* c, const uint32_t* a,
                                          uint32_t b0, uint32_t b1) {
    asm volatile("mma.sync.aligned.m16n8k16.row.col.f32.f16.f16.f32 "
        "{%0,%1,%2,%3}, {%4,%5,%6,%7}, {%8,%9}, {%0,%1,%2,%3};"
        : "+f"(c[0]), "+f"(c[1]), "+f"(c[2]), "+f"(c[3])
        : "r"(a[0]), "r"(a[1]), "r"(a[2]), "r"(a[3]), "r"(b0), "r"(b1));
}
// Isolated dot: D = A*B + 0 (exact, bias-free) -- phase-2 a0*b0.
__device__ __forceinline__ void mma_zero(float* d, const uint32_t* a,
                                         uint32_t b0, uint32_t b1) {
    asm volatile("mma.sync.aligned.m16n8k16.row.col.f32.f16.f16.f32 "
        "{%0,%1,%2,%3}, {%4,%5,%6,%7}, {%8,%9}, {%10,%10,%10,%10};"
        : "=f"(d[0]), "=f"(d[1]), "=f"(d[2]), "=f"(d[3])
        : "r"(a[0]), "r"(a[1]), "r"(a[2]), "r"(a[3]), "r"(b0), "r"(b1),
          "f"(0.0f));
}

// ---------------- Kernel A: fp32 -> 2-way fp16 split (x and W fused) -------
__device__ __forceinline__ void split2_store(__half* base, size_t row,
                                             int col, const float* vv) {
    __align__(8) __half t0[4], t1[4];
    #pragma unroll
    for (int j = 0; j < 4; j++) {
        const float a = vv[j];
        t0[j] = __float2half_rn(a);
        t1[j] = __float2half_rn(a - __half2float(t0[j]));
    }
    *reinterpret_cast<uint2*>(&base[row * KW + col])       = *reinterpret_cast<uint2*>(t0);
    *reinterpret_cast<uint2*>(&base[row * KW + 512 + col]) = *reinterpret_cast<uint2*>(t1);
}
#define X_BLOCKS ((M_TOTAL * IN_F / 4) / 256)    // 12800
#define W_BLOCKS ((HID * IN_F / 4) / 256)        // 512
__global__ void convert_xw(const float* __restrict__ x, const float* __restrict__ w) {
    if (blockIdx.x < X_BLOCKS) {
        size_t i = (size_t)blockIdx.x * blockDim.x + threadIdx.x;
        float4 v = reinterpret_cast<const float4*>(x)[i];
        size_t f = i * 4;
        float vv[4] = {v.x, v.y, v.z, v.w};
        split2_store(g_A2, f >> 9, (int)(f & 511), vv);
    } else {
        size_t i = (size_t)(blockIdx.x - X_BLOCKS) * blockDim.x + threadIdx.x;
        float4 v = reinterpret_cast<const float4*>(w)[i];
        size_t f = i * 4;
        float vv[4] = {v.x, v.y, v.z, v.w};
        split2_store(g_B2, f >> 9, (int)(f & 511), vv);
    }
}

// ---------------- GEMM helpers ---------------------------------------------
__constant__ int2 SEG_COLS[3] = {
    {0, 512},     // a0*b1   (2^-11, fully TC-chained)
    {512, 0},     // a1*b0   (2^-11, fully TC-chained)
    {0, 0},       // a0*b0   (1)  -- isolated mma + FADD fold
};
#define NCHUNKS 24
#define SMEM_BYTES 49152     // A 2x16KB + B 2x8KB

// chunk loader for a 128(m) x 64(n) tile
__device__ __forceinline__ void load_chunk(int c, uint32_t sAst, uint32_t sBst,
                                           int tid, int mbase, int nbase) {
    const int2 sc = SEG_COLS[c >> 3];
    const int kk = (c & 7) * 64;
    const int a_col = sc.x + kk;
    const int b_col = sc.y + kk;
    #pragma unroll
    for (int p = 0; p < 4; p++) {            // A: 128 rows x 128B
        const int o   = tid + p * 256;
        const int row = o >> 3;
        const int q   = o & 7;
        const uint32_t dst = sAst + row * 128 + ((q * 16) ^ ((row & 7) << 4));
        cp16(dst, &g_A2[(size_t)(mbase + row) * KW + a_col + q * 8]);
    }
    #pragma unroll
    for (int p = 0; p < 2; p++) {            // B: 64 rows x 128B
        const int o   = tid + p * 256;
        const int row = o >> 3;
        const int q   = o & 7;
        const uint32_t dst = sBst + row * 128 + ((q * 16) ^ ((row & 7) << 4));
        cp16(dst, &g_B2[(size_t)(nbase + row) * KW + b_col + q * 8]);
    }
    CP_COMMIT();
}

// ---------------- Kernel B: fp16 mma GEMM, 128x64 tile, occupancy 3 --------
// 8 warps in 4(m) x 2(n); warp tile 32x32 (acc=32 regs); 6 warps/SMSP.
__global__ __launch_bounds__(256, 3)
void gemm_fc1_mma(const float* __restrict__ b1) {
    extern __shared__ char smem[];
    const uint32_t sb = smem_u32(smem);
    const int tid  = threadIdx.x;
    const int lane = tid & 31;
    const int wid  = tid >> 5;
    const int wm   = wid >> 1;         // 0..3  (m)
    const int wn   = wid & 1;          // 0..1  (n)
    const int mbase = blockIdx.y * 128;
    const int nbase = blockIdx.x * 64;

    const uint32_t sA[2] = {sb, sb + 16384};
    const uint32_t sB[2] = {sb + 32768, sb + 40960};

    float acc[2][4][4];                // [mm][n8 blk][e] = 32 regs

    const int lrow  = lane & 15;
    const int lhalf = (lane >> 4) * 16;

    load_chunk(0, sA[0], sB[0], tid, mbase, nbase);

    for (int c = 0; c < NCHUNKS; c++) {
        const int st = c & 1;
        if (c < NCHUNKS - 1) {
            load_chunk(c + 1, sA[st ^ 1], sB[st ^ 1], tid, mbase, nbase);
            CP_WAIT(1);
        } else {
            CP_WAIT(0);
        }
        __syncthreads();

        #pragma unroll
        for (int ks = 0; ks < 4; ks++) {
            const int cb = ks * 32 + lhalf;
            uint32_t a[2][4], b[2][4];
            #pragma unroll
            for (int mm = 0; mm < 2; mm++) {
                const int row = wm * 32 + mm * 16 + lrow;
                ldm_x4(a[mm], sA[st] + row * 128 + (cb ^ ((row & 7) << 4)));
            }
            #pragma unroll
            for (int bq = 0; bq < 2; bq++) {
                const int row = wn * 32 + bq * 16 + lrow;
                ldm_x4(b[bq], sB[st] + row * 128 + (cb ^ ((row & 7) << 4)));
            }
            if (c == 0 && ks == 0) {
                #pragma unroll
                for (int mm = 0; mm < 2; mm++)
                    #pragma unroll
                    for (int bq = 0; bq < 2; bq++) {
                        mma_zero(acc[mm][bq * 2],     a[mm], b[bq][0], b[bq][2]);
                        mma_zero(acc[mm][bq * 2 + 1], a[mm], b[bq][1], b[bq][3]);
                    }
            } else if (c < 16) {
                #pragma unroll
                for (int mm = 0; mm < 2; mm++)
                    #pragma unroll
                    for (int bq = 0; bq < 2; bq++) {
                        mma_chain(acc[mm][bq * 2],     a[mm], b[bq][0], b[bq][2]);
                        mma_chain(acc[mm][bq * 2 + 1], a[mm], b[bq][1], b[bq][3]);
                    }
            } else {
                #pragma unroll
                for (int mm = 0; mm < 2; mm++)
                    #pragma unroll
                    for (int bq = 0; bq < 2; bq++) {
                        float t0[4], t1[4];
                        mma_zero(t0, a[mm], b[bq][0], b[bq][2]);
                        mma_zero(t1, a[mm], b[bq][1], b[bq][3]);
                        #pragma unroll
                        for (int e = 0; e < 4; e++) {
                            acc[mm][bq * 2][e]     += t0[e];
                            acc[mm][bq * 2 + 1][e] += t1[e];
                        }
                    }
            }
        }
        __syncthreads();
    }

    // Epilogue: bias + store f32 to g_cur.
    const int qrow = lane >> 2;
    const int qcol = (lane & 3) * 2;
    #pragma unroll
    for (int nb = 0; nb < 4; nb++) {
        const int n = nbase + wn * 32 + nb * 8 + qcol;
        const float bv0 = b1[n], bv1 = b1[n + 1];
        #pragma unroll
        for (int mm = 0; mm < 2; mm++) {
            const int r0 = mbase + wm * 32 + mm * 16 + qrow;
            float2 v0 = make_float2(acc[mm][nb][0] + bv0, acc[mm][nb][1] + bv1);
            float2 v1 = make_float2(acc[mm][nb][2] + bv0, acc[mm][nb][3] + bv1);
            *reinterpret_cast<float2*>(&g_cur[(size_t)r0 * 1024 + n])       = v0;
            *reinterpret_cast<float2*>(&g_cur[(size_t)(r0 + 8) * 1024 + n]) = v1;
        }
    }
}

// ---------------- Kernel C: LIF scan (float4, 1 block/b, writes out) -------
__global__ __launch_bounds__(256, 4)
void lif_fused(const float* __restrict__ W2, const float* __restrict__ b2,
               float* __restrict__ out) {
    const int b  = blockIdx.x;
    const int h0 = threadIdx.x * 4;
    const float4* p = reinterpret_cast<const float4*>(
                          g_cur + (size_t)b * T_STEPS * HID) + threadIdx.x;

    float m0 = 0.f, m1 = 0.f, m2 = 0.f, m3 = 0.f;
    float s0 = 0.f, s1 = 0.f, s2 = 0.f, s3 = 0.f;
    #pragma unroll 4
    for (int t = 0; t < T_STEPS; t++) {
        const float4 c = p[t * 256];
        m0 = 0.9f * m0 + c.x - ((m0 > 1.0f) ? 1.0f : 0.0f);
        m1 = 0.9f * m1 + c.y - ((m1 > 1.0f) ? 1.0f : 0.0f);
        m2 = 0.9f * m2 + c.z - ((m2 > 1.0f) ? 1.0f : 0.0f);
        m3 = 0.9f * m3 + c.w - ((m3 > 1.0f) ? 1.0f : 0.0f);
        s0 += (m0 > 1.0f) ? 1.0f : 0.0f;
        s1 += (m1 > 1.0f) ? 1.0f : 0.0f;
        s2 += (m2 > 1.0f) ? 1.0f : 0.0f;
        s3 += (m3 > 1.0f) ? 1.0f : 0.0f;
    }

    float part[8];
    #pragma unroll
    for (int c = 0; c < 8; c++) {
        const float* w = &W2[c * HID + h0];
        part[c] = s0 * w[0] + s1 * w[1] + s2 * w[2] + s3 * w[3];
    }
    #pragma unroll
    for (int c = 0; c < 8; c++)
        #pragma unroll
        for (int o = 16; o > 0; o >>= 1)
            part[c] += __shfl_down_sync(0xffffffffu, part[c], o);

    __shared__ float s_red[8][8];
    const int lane = threadIdx.x & 31, warp = threadIdx.x >> 5;   // 8 warps
    if (lane == 0)
        #pragma unroll
        for (int c = 0; c < 8; c++) s_red[c][warp] = part[c];
    __syncthreads();
    if (threadIdx.x < 64) {
        const int c = threadIdx.x >> 3, w = threadIdx.x & 7;
        float v = s_red[c][w];
        #pragma unroll
        for (int o = 4; o > 0; o >>= 1)
            v += __shfl_down_sync(0xffffffffu, v, o, 8);
        if (w == 0) out[b * CLS + c] = v + 100.0f * b2[c];
    }
}

// ---------------------------------------------------------------------------
extern "C" void kernel_launch(void* const* d_in, const int* in_sizes, int n_in,
                              void* d_out, int out_size) {
    const float* x  = (const float*)d_in[0];
    const float* W1 = (const float*)d_in[1];
    const float* b1 = (const float*)d_in[2];
    const float* W2 = (const float*)d_in[3];
    const float* b2 = (const float*)d_in[4];
    float* out = (float*)d_out;

    cudaFuncSetAttribute(gemm_fc1_mma, cudaFuncAttributeMaxDynamicSharedMemorySize,
                         SMEM_BYTES);

    convert_xw<<<X_BLOCKS + W_BLOCKS, 256>>>(x, W1);
    // grid: x = n-tiles (16) fastest -> CTAs sharing an A chunk co-scheduled
    gemm_fc1_mma<<<dim3(HID / 64, M_TOTAL / 128), 256, SMEM_BYTES>>>(b1);
    lif_fused<<<B_SZ, 256>>>(W2, b2, out);
}

// round 15
// speedup vs baseline: 1.0630x; 1.0630x over previous
#include <cuda_runtime.h>
#include <cuda_fp16.h>
#include <cstdint>

// Shapes: x[256,100,512] f32, W1[1024,512] f32, b1[1024], W2[8,1024], b2[8]
// out[256,8] f32.
#define T_STEPS 100
#define B_SZ    256
#define IN_F    512
#define HID     1024
#define CLS     8
#define M_TOTAL (B_SZ * T_STEPS)   // 25600
#define KW      1024               // 2 fp16 terms x 512

// ---------------- device scratch (static; no allocations) -----------------
__device__ float  g_cur[(size_t)M_TOTAL * HID];   // 104.9 MB
__device__ __half g_A2[(size_t)M_TOTAL * KW];     // [m][a0|a1] 52.4 MB
__device__ __half g_B2[(size_t)HID * KW];         // [n][b0|b1]  2.1 MB

// ---------------- base-PTX helpers (sm_80+) --------------------------------
__device__ __forceinline__ uint32_t smem_u32(const void* p) {
    uint32_t a;
    asm("{ .reg .u64 t; cvta.to.shared.u64 t, %1; cvt.u32.u64 %0, t; }" : "=r"(a) : "l"(p));
    return a;
}
__device__ __forceinline__ void cp16(uint32_t dst, const void* src) {
    asm volatile("cp.async.cg.shared.global [%0], [%1], 16;" :: "r"(dst), "l"(src));
}
#define CP_COMMIT() asm volatile("cp.async.commit_group;")
#define CP_WAIT(n)  asm volatile("cp.async.wait_group %0;" :: "n"(n))

__device__ __forceinline__ void ldm_x4(uint32_t* r, uint32_t addr) {
    asm volatile("ldmatrix.sync.aligned.m8n8.x4.shared.b16 {%0,%1,%2,%3}, [%4];"
        : "=r"(r[0]), "=r"(r[1]), "=r"(r[2]), "=r"(r[3]) : "r"(addr));
}
// Chained mma: D += A*B through the TC accumulator (RZ-biased add; safe only
// while |acc| stays ~2^-11 -- phase-1 segments).
__device__ __forceinline__ void mma_chain(float* c, const uint32_t* a,
                                          uint32_t b0, uint32_t b1) {
    asm volatile("mma.sync.aligned.m16n8k16.row.col.f32.f16.f16.f32 "
        "{%0,%1,%2,%3}, {%4,%5,%6,%7}, {%8,%9}, {%0,%1,%2,%3};"
        : "+f"(c[0]), "+f"(c[1]), "+f"(c[2]), "+f"(c[3])
        : "r"(a[0]), "r"(a[1]), "r"(a[2]), "r"(a[3]), "r"(b0), "r"(b1));
}
// Isolated dot: D = A*B + 0 (exact, bias-free) -- phase-2 a0*b0.
__device__ __forceinline__ void mma_zero(float* d, const uint32_t* a,
                                         uint32_t b0, uint32_t b1) {
    asm volatile("mma.sync.aligned.m16n8k16.row.col.f32.f16.f16.f32 "
        "{%0,%1,%2,%3}, {%4,%5,%6,%7}, {%8,%9}, {%10,%10,%10,%10};"
        : "=f"(d[0]), "=f"(d[1]), "=f"(d[2]), "=f"(d[3])
        : "r"(a[0]), "r"(a[1]), "r"(a[2]), "r"(a[3]), "r"(b0), "r"(b1),
          "f"(0.0f));
}

// ---------------- Kernel A: fp32 -> 2-way fp16 split (x and W fused) -------
__device__ __forceinline__ void split2_store(__half* base, size_t row,
                                             int col, const float* vv) {
    __align__(8) __half t0[4], t1[4];
    #pragma unroll
    for (int j = 0; j < 4; j++) {
        const float a = vv[j];
        t0[j] = __float2half_rn(a);
        t1[j] = __float2half_rn(a - __half2float(t0[j]));
    }
    *reinterpret_cast<uint2*>(&base[row * KW + col])       = *reinterpret_cast<uint2*>(t0);
    *reinterpret_cast<uint2*>(&base[row * KW + 512 + col]) = *reinterpret_cast<uint2*>(t1);
}
#define X_BLOCKS ((M_TOTAL * IN_F / 4) / 256)    // 12800
#define W_BLOCKS ((HID * IN_F / 4) / 256)        // 512
__global__ void convert_xw(const float* __restrict__ x, const float* __restrict__ w) {
    if (blockIdx.x < X_BLOCKS) {
        size_t i = (size_t)blockIdx.x * blockDim.x + threadIdx.x;
        float4 v = reinterpret_cast<const float4*>(x)[i];
        size_t f = i * 4;
        float vv[4] = {v.x, v.y, v.z, v.w};
        split2_store(g_A2, f >> 9, (int)(f & 511), vv);
    } else {
        size_t i = (size_t)(blockIdx.x - X_BLOCKS) * blockDim.x + threadIdx.x;
        float4 v = reinterpret_cast<const float4*>(w)[i];
        size_t f = i * 4;
        float vv[4] = {v.x, v.y, v.z, v.w};
        split2_store(g_B2, f >> 9, (int)(f & 511), vv);
    }
}

// ---------------- GEMM helpers (champion R10 path, 3-stage ring) -----------
__constant__ int2 SEG_COLS[3] = {
    {0, 512},     // a0*b1   (2^-11, fully TC-chained)
    {512, 0},     // a1*b0   (2^-11, fully TC-chained)
    {0, 0},       // a0*b0   (1)  -- isolated mma + FADD fold
};
#define NCHUNKS 24
#define SMEM_BYTES 98304     // 3 x (A 16KB + B 16KB)

__device__ __forceinline__ void load_chunk(int c, uint32_t sAst, uint32_t sBst,
                                           int tid, int mbase, int nbase) {
    const int2 sc = SEG_COLS[c >> 3];
    const int kk = (c & 7) * 64;
    const int a_col = sc.x + kk;
    const int b_col = sc.y + kk;
    #pragma unroll
    for (int p = 0; p < 4; p++) {            // A: 128 rows x 128B
        const int o   = tid + p * 256;
        const int row = o >> 3;
        const int q   = o & 7;
        const uint32_t dst = sAst + row * 128 + ((q * 16) ^ ((row & 7) << 4));
        cp16(dst, &g_A2[(size_t)(mbase + row) * KW + a_col + q * 8]);
    }
    #pragma unroll
    for (int p = 0; p < 4; p++) {            // B: 128 rows x 128B
        const int o   = tid + p * 256;
        const int row = o >> 3;
        const int q   = o & 7;
        const uint32_t dst = sBst + row * 128 + ((q * 16) ^ ((row & 7) << 4));
        cp16(dst, &g_B2[(size_t)(nbase + row) * KW + b_col + q * 8]);
    }
    CP_COMMIT();
}

// ---------------- Kernel B: fp16 mma GEMM, 128x128 tile, occupancy 2 -------
// Champion config (R10) with a 3-stage cp.async ring: ONE __syncthreads per
// chunk (the sync both publishes chunk c and retires all reads of the stage
// about to be overwritten by chunk c+2), prefetch depth 2.
__global__ __launch_bounds__(256, 2)
void gemm_fc1_mma(const float* __restrict__ b1) {
    extern __shared__ char smem[];
    const uint32_t sb = smem_u32(smem);
    const int tid  = threadIdx.x;
    const int lane = tid & 31;
    const int wid  = tid >> 5;
    const int wm   = wid >> 2;         // 0..1  (m)
    const int wn   = wid & 3;          // 0..3  (n)
    const int mbase = blockIdx.y * 128;
    const int nbase = blockIdx.x * 128;

    const uint32_t sA[3] = {sb,         sb + 16384, sb + 32768};
    const uint32_t sB[3] = {sb + 49152, sb + 65536, sb + 81920};

    float acc[4][4][4];                // [mm][n8 blk][e] = 64 regs

    const int lrow  = lane & 15;
    const int lhalf = (lane >> 4) * 16;

    load_chunk(0, sA[0], sB[0], tid, mbase, nbase);
    load_chunk(1, sA[1], sB[1], tid, mbase, nbase);

    #pragma unroll 1
    for (int c = 0; c < NCHUNKS; c++) {
        const int st = c % 3;
        // chunk c landed (leave <=1 group in flight), and all warps are past
        // iteration c-1 (so stage (c+2)%3 == (c-1)%3 is free to overwrite).
        if (c < NCHUNKS - 1) CP_WAIT(1); else CP_WAIT(0);
        __syncthreads();
        if (c + 2 < NCHUNKS)
            load_chunk(c + 2, sA[(c + 2) % 3], sB[(c + 2) % 3],
                       tid, mbase, nbase);

        #pragma unroll
        for (int ks = 0; ks < 4; ks++) {
            const int cb = ks * 32 + lhalf;
            uint32_t a[4][4], b[2][4];
            #pragma unroll
            for (int mm = 0; mm < 4; mm++) {
                const int row = wm * 64 + mm * 16 + lrow;
                ldm_x4(a[mm], sA[st] + row * 128 + (cb ^ ((row & 7) << 4)));
            }
            #pragma unroll
            for (int bq = 0; bq < 2; bq++) {
                const int row = wn * 32 + bq * 16 + lrow;
                ldm_x4(b[bq], sB[st] + row * 128 + (cb ^ ((row & 7) << 4)));
            }
            if (c == 0 && ks == 0) {
                #pragma unroll
                for (int mm = 0; mm < 4; mm++)
                    #pragma unroll
                    for (int bq = 0; bq < 2; bq++) {
                        mma_zero(acc[mm][bq * 2],     a[mm], b[bq][0], b[bq][2]);
                        mma_zero(acc[mm][bq * 2 + 1], a[mm], b[bq][1], b[bq][3]);
                    }
            } else if (c < 16) {
                #pragma unroll
                for (int mm = 0; mm < 4; mm++)
                    #pragma unroll
                    for (int bq = 0; bq < 2; bq++) {
                        mma_chain(acc[mm][bq * 2],     a[mm], b[bq][0], b[bq][2]);
                        mma_chain(acc[mm][bq * 2 + 1], a[mm], b[bq][1], b[bq][3]);
                    }
            } else {
                #pragma unroll
                for (int mm = 0; mm < 4; mm++)
                    #pragma unroll
                    for (int bq = 0; bq < 2; bq++) {
                        float t0[4], t1[4];
                        mma_zero(t0, a[mm], b[bq][0], b[bq][2]);
                        mma_zero(t1, a[mm], b[bq][1], b[bq][3]);
                        #pragma unroll
                        for (int e = 0; e < 4; e++) {
                            acc[mm][bq * 2][e]     += t0[e];
                            acc[mm][bq * 2 + 1][e] += t1[e];
                        }
                    }
            }
        }
    }

    // Epilogue: bias + store f32 to g_cur.
    const int qrow = lane >> 2;
    const int qcol = (lane & 3) * 2;
    #pragma unroll
    for (int nb = 0; nb < 4; nb++) {
        const int n = nbase + wn * 32 + nb * 8 + qcol;
        const float bv0 = b1[n], bv1 = b1[n + 1];
        #pragma unroll
        for (int mm = 0; mm < 4; mm++) {
            const int r0 = mbase + wm * 64 + mm * 16 + qrow;
            float2 v0 = make_float2(acc[mm][nb][0] + bv0, acc[mm][nb][1] + bv1);
            float2 v1 = make_float2(acc[mm][nb][2] + bv0, acc[mm][nb][3] + bv1);
            *reinterpret_cast<float2*>(&g_cur[(size_t)r0 * 1024 + n])       = v0;
            *reinterpret_cast<float2*>(&g_cur[(size_t)(r0 + 8) * 1024 + n]) = v1;
        }
    }
}

// ---------------- Kernel C: LIF scan + fused output GEMM (R10 champion) ----
__global__ __launch_bounds__(1024, 1)
void lif_reduce(const float* __restrict__ W2, const float* __restrict__ b2,
                float* __restrict__ out) {
    const int b = blockIdx.x;
    const int h = threadIdx.x;
    const float* p = g_cur + (size_t)b * T_STEPS * HID + h;

    float mem = 0.0f, spk_sum = 0.0f;
    #pragma unroll 4
    for (int t = 0; t < T_STEPS; t++) {
        const float c = p[t * HID];
        const float reset = (mem > 1.0f) ? 1.0f : 0.0f;
        mem = 0.9f * mem + c - reset;
        spk_sum += (mem > 1.0f) ? 1.0f : 0.0f;
    }
    float part[8];
    #pragma unroll
    for (int c = 0; c < 8; c++) part[c] = spk_sum * W2[c * HID + h];
    #pragma unroll
    for (int c = 0; c < 8; c++)
        #pragma unroll
        for (int o = 16; o > 0; o >>= 1)
            part[c] += __shfl_down_sync(0xffffffffu, part[c], o);

    __shared__ float s_red[8][32];
    const int lane = h & 31, warp = h >> 5;
    if (lane == 0)
        #pragma unroll
        for (int c = 0; c < 8; c++) s_red[c][warp] = part[c];
    __syncthreads();
    if (threadIdx.x < 256) {
        const int c = threadIdx.x >> 5, w = threadIdx.x & 31;
        float v = s_red[c][w];
        #pragma unroll
        for (int o = 16; o > 0; o >>= 1)
            v += __shfl_down_sync(0xffffffffu, v, o);
        if (w == 0) out[b * CLS + c] = v + 100.0f * b2[c];
    }
}

// ---------------------------------------------------------------------------
extern "C" void kernel_launch(void* const* d_in, const int* in_sizes, int n_in,
                              void* d_out, int out_size) {
    const float* x  = (const float*)d_in[0];
    const float* W1 = (const float*)d_in[1];
    const float* b1 = (const float*)d_in[2];
    const float* W2 = (const float*)d_in[3];
    const float* b2 = (const float*)d_in[4];
    float* out = (float*)d_out;

    cudaFuncSetAttribute(gemm_fc1_mma, cudaFuncAttributeMaxDynamicSharedMemorySize,
                         SMEM_BYTES);

    convert_xw<<<X_BLOCKS + W_BLOCKS, 256>>>(x, W1);
    // grid: x = n-tiles (8) fastest -> CTAs sharing an A chunk co-scheduled
    gemm_fc1_mma<<<dim3(HID / 128, M_TOTAL / 128), 256, SMEM_BYTES>>>(b1);
    lif_reduce<<<B_SZ, 1024>>>(W2, b2, out);
}

// round 16
// speedup vs baseline: 1.0932x; 1.0284x over previous
#include <cuda_runtime.h>
#include <cuda_fp16.h>
#include <cstdint>

// Shapes: x[256,100,512] f32, W1[1024,512] f32, b1[1024], W2[8,1024], b2[8]
// out[256,8] f32.
#define T_STEPS 100
#define B_SZ    256
#define IN_F    512
#define HID     1024
#define CLS     8
#define M_TOTAL (B_SZ * T_STEPS)   // 25600
#define KW      1024               // 2 fp16 terms x 512

// ---------------- device scratch (static; no allocations) -----------------
__device__ float  g_cur[(size_t)M_TOTAL * HID];   // 104.9 MB
__device__ __half g_A2[(size_t)M_TOTAL * KW];     // [m][a0|a1] 52.4 MB
__device__ __half g_B2[(size_t)HID * KW];         // [n][b0|b1]  2.1 MB

// ---------------- base-PTX helpers (sm_80+) --------------------------------
__device__ __forceinline__ uint32_t smem_u32(const void* p) {
    uint32_t a;
    asm("{ .reg .u64 t; cvta.to.shared.u64 t, %1; cvt.u32.u64 %0, t; }" : "=r"(a) : "l"(p));
    return a;
}
__device__ __forceinline__ void cp16(uint32_t dst, const void* src) {
    asm volatile("cp.async.cg.shared.global [%0], [%1], 16;" :: "r"(dst), "l"(src));
}
#define CP_COMMIT() asm volatile("cp.async.commit_group;")
#define CP_WAIT(n)  asm volatile("cp.async.wait_group %0;" :: "n"(n))

__device__ __forceinline__ void ldm_x4(uint32_t* r, uint32_t addr) {
    asm volatile("ldmatrix.sync.aligned.m8n8.x4.shared.b16 {%0,%1,%2,%3}, [%4];"
        : "=r"(r[0]), "=r"(r[1]), "=r"(r[2]), "=r"(r[3]) : "r"(addr));
}
// Chained mma: D += A*B through the TC accumulator (RZ-biased add; safe only
// while |acc| stays ~2^-11 -- phase-1 segments).
__device__ __forceinline__ void mma_chain(float* c, const uint32_t* a,
                                          uint32_t b0, uint32_t b1) {
    asm volatile("mma.sync.aligned.m16n8k16.row.col.f32.f16.f16.f32 "
        "{%0,%1,%2,%3}, {%4,%5,%6,%7}, {%8,%9}, {%0,%1,%2,%3};"
        : "+f"(c[0]), "+f"(c[1]), "+f"(c[2]), "+f"(c[3])
        : "r"(a[0]), "r"(a[1]), "r"(a[2]), "r"(a[3]), "r"(b0), "r"(b1));
}
// Isolated dot: D = A*B + 0 (exact, bias-free) -- phase-2 a0*b0.
__device__ __forceinline__ void mma_zero(float* d, const uint32_t* a,
                                         uint32_t b0, uint32_t b1) {
    asm volatile("mma.sync.aligned.m16n8k16.row.col.f32.f16.f16.f32 "
        "{%0,%1,%2,%3}, {%4,%5,%6,%7}, {%8,%9}, {%10,%10,%10,%10};"
        : "=f"(d[0]), "=f"(d[1]), "=f"(d[2]), "=f"(d[3])
        : "r"(a[0]), "r"(a[1]), "r"(a[2]), "r"(a[3]), "r"(b0), "r"(b1),
          "f"(0.0f));
}

// ---------------- Kernel A: fp32 -> 2-way fp16 split -----------------------
// 8 floats per thread (2x LDG.128 evict-first + 2x STG.128): doubled MLP,
// halved grid/issue count vs the 4-float version.
#define X_BLOCKS ((M_TOTAL * IN_F / 8) / 256)    // 6400
#define W_BLOCKS ((HID * IN_F / 8) / 256)        // 256
__device__ __forceinline__ void split2_store8(__half* base, const float* src,
                                              size_t i) {
    const size_t f = i * 8;
    const size_t row = f >> 9;
    const int    col = (int)(f & 511);
    const float4 v0 = __ldcs(reinterpret_cast<const float4*>(src) + i * 2);
    const float4 v1 = __ldcs(reinterpret_cast<const float4*>(src) + i * 2 + 1);
    const float vv[8] = {v0.x, v0.y, v0.z, v0.w, v1.x, v1.y, v1.z, v1.w};
    __align__(16) __half t0[8], t1[8];
    #pragma unroll
    for (int j = 0; j < 8; j++) {
        const float a = vv[j];
        t0[j] = __float2half_rn(a);
        t1[j] = __float2half_rn(a - __half2float(t0[j]));
    }
    *reinterpret_cast<uint4*>(&base[row * KW + col])       = *reinterpret_cast<uint4*>(t0);
    *reinterpret_cast<uint4*>(&base[row * KW + 512 + col]) = *reinterpret_cast<uint4*>(t1);
}
__global__ void convert_xw(const float* __restrict__ x, const float* __restrict__ w) {
    if (blockIdx.x < X_BLOCKS) {
        split2_store8(g_A2, x, (size_t)blockIdx.x * blockDim.x + threadIdx.x);
    } else {
        split2_store8(g_B2, w,
            (size_t)(blockIdx.x - X_BLOCKS) * blockDim.x + threadIdx.x);
    }
}

// ---------------- GEMM helpers (champion R10 path) --------------------------
__constant__ int2 SEG_COLS[3] = {
    {0, 512},     // a0*b1   (2^-11, fully TC-chained)
    {512, 0},     // a1*b0   (2^-11, fully TC-chained)
    {0, 0},       // a0*b0   (1)  -- isolated mma + FADD fold
};
#define NCHUNKS 24
#define SMEM_BYTES 65536

__device__ __forceinline__ void load_chunk(int c, uint32_t sAst, uint32_t sBst,
                                           int tid, int mbase, int nbase) {
    const int2 sc = SEG_COLS[c >> 3];
    const int kk = (c & 7) * 64;
    const int a_col = sc.x + kk;
    const int b_col = sc.y + kk;
    #pragma unroll
    for (int p = 0; p < 4; p++) {            // A: 128 rows x 128B
        const int o   = tid + p * 256;
        const int row = o >> 3;
        const int q   = o & 7;
        const uint32_t dst = sAst + row * 128 + ((q * 16) ^ ((row & 7) << 4));
        cp16(dst, &g_A2[(size_t)(mbase + row) * KW + a_col + q * 8]);
    }
    #pragma unroll
    for (int p = 0; p < 4; p++) {            // B: 128 rows x 128B
        const int o   = tid + p * 256;
        const int row = o >> 3;
        const int q   = o & 7;
        const uint32_t dst = sBst + row * 128 + ((q * 16) ^ ((row & 7) << 4));
        cp16(dst, &g_B2[(size_t)(nbase + row) * KW + b_col + q * 8]);
    }
    CP_COMMIT();
}

// ---------------- Kernel B: fp16 mma GEMM, 128x128 tile, occupancy 2 -------
// (R10 champion, byte-identical: at the legacy-HMMA issue floor.)
__global__ __launch_bounds__(256, 2)
void gemm_fc1_mma(const float* __restrict__ b1) {
    extern __shared__ char smem[];
    const uint32_t sb = smem_u32(smem);
    const int tid  = threadIdx.x;
    const int lane = tid & 31;
    const int wid  = tid >> 5;
    const int wm   = wid >> 2;         // 0..1  (m)
    const int wn   = wid & 3;          // 0..3  (n)
    const int mbase = blockIdx.y * 128;
    const int nbase = blockIdx.x * 128;

    const uint32_t sA[2] = {sb, sb + 16384};
    const uint32_t sB[2] = {sb + 32768, sb + 49152};

    float acc[4][4][4];                // [mm][n8 blk][e] = 64 regs

    const int lrow  = lane & 15;
    const int lhalf = (lane >> 4) * 16;

    load_chunk(0, sA[0], sB[0], tid, mbase, nbase);

    for (int c = 0; c < NCHUNKS; c++) {
        const int st = c & 1;
        if (c < NCHUNKS - 1) {
            load_chunk(c + 1, sA[st ^ 1], sB[st ^ 1], tid, mbase, nbase);
            CP_WAIT(1);
        } else {
            CP_WAIT(0);
        }
        __syncthreads();

        #pragma unroll
        for (int ks = 0; ks < 4; ks++) {
            const int cb = ks * 32 + lhalf;
            uint32_t a[4][4], b[2][4];
            #pragma unroll
            for (int mm = 0; mm < 4; mm++) {
                const int row = wm * 64 + mm * 16 + lrow;
                ldm_x4(a[mm], sA[st] + row * 128 + (cb ^ ((row & 7) << 4)));
            }
            #pragma unroll
            for (int bq = 0; bq < 2; bq++) {
                const int row = wn * 32 + bq * 16 + lrow;
                ldm_x4(b[bq], sB[st] + row * 128 + (cb ^ ((row & 7) << 4)));
            }
            if (c == 0 && ks == 0) {
                #pragma unroll
                for (int mm = 0; mm < 4; mm++)
                    #pragma unroll
                    for (int bq = 0; bq < 2; bq++) {
                        mma_zero(acc[mm][bq * 2],     a[mm], b[bq][0], b[bq][2]);
                        mma_zero(acc[mm][bq * 2 + 1], a[mm], b[bq][1], b[bq][3]);
                    }
            } else if (c < 16) {
                #pragma unroll
                for (int mm = 0; mm < 4; mm++)
                    #pragma unroll
                    for (int bq = 0; bq < 2; bq++) {
                        mma_chain(acc[mm][bq * 2],     a[mm], b[bq][0], b[bq][2]);
                        mma_chain(acc[mm][bq * 2 + 1], a[mm], b[bq][1], b[bq][3]);
                    }
            } else {
                #pragma unroll
                for (int mm = 0; mm < 4; mm++)
                    #pragma unroll
                    for (int bq = 0; bq < 2; bq++) {
                        float t0[4], t1[4];
                        mma_zero(t0, a[mm], b[bq][0], b[bq][2]);
                        mma_zero(t1, a[mm], b[bq][1], b[bq][3]);
                        #pragma unroll
                        for (int e = 0; e < 4; e++) {
                            acc[mm][bq * 2][e]     += t0[e];
                            acc[mm][bq * 2 + 1][e] += t1[e];
                        }
                    }
            }
        }
        __syncthreads();
    }

    // Epilogue: bias + store f32 to g_cur.
    const int qrow = lane >> 2;
    const int qcol = (lane & 3) * 2;
    #pragma unroll
    for (int nb = 0; nb < 4; nb++) {
        const int n = nbase + wn * 32 + nb * 8 + qcol;
        const float bv0 = b1[n], bv1 = b1[n + 1];
        #pragma unroll
        for (int mm = 0; mm < 4; mm++) {
            const int r0 = mbase + wm * 64 + mm * 16 + qrow;
            float2 v0 = make_float2(acc[mm][nb][0] + bv0, acc[mm][nb][1] + bv1);
            float2 v1 = make_float2(acc[mm][nb][2] + bv0, acc[mm][nb][3] + bv1);
            *reinterpret_cast<float2*>(&g_cur[(size_t)r0 * 1024 + n])       = v0;
            *reinterpret_cast<float2*>(&g_cur[(size_t)(r0 + 8) * 1024 + n]) = v1;
        }
    }
}

// ---------------- Kernel C: LIF scan + fused output GEMM (R10 champion) ----
__global__ __launch_bounds__(1024, 1)
void lif_reduce(const float* __restrict__ W2, const float* __restrict__ b2,
                float* __restrict__ out) {
    const int b = blockIdx.x;
    const int h = threadIdx.x;
    const float* p = g_cur + (size_t)b * T_STEPS * HID + h;

    float mem = 0.0f, spk_sum = 0.0f;
    #pragma unroll 4
    for (int t = 0; t < T_STEPS; t++) {
        const float c = __ldcs(&p[t * HID]);    // read-once stream
        const float reset = (mem > 1.0f) ? 1.0f : 0.0f;
        mem = 0.9f * mem + c - reset;
        spk_sum += (mem > 1.0f) ? 1.0f : 0.0f;
    }
    float part[8];
    #pragma unroll
    for (int c = 0; c < 8; c++) part[c] = spk_sum * W2[c * HID + h];
    #pragma unroll
    for (int c = 0; c < 8; c++)
        #pragma unroll
        for (int o = 16; o > 0; o >>= 1)
            part[c] += __shfl_down_sync(0xffffffffu, part[c], o);

    __shared__ float s_red[8][32];
    const int lane = h & 31, warp = h >> 5;
    if (lane == 0)
        #pragma unroll
        for (int c = 0; c < 8; c++) s_red[c][warp] = part[c];
    __syncthreads();
    if (threadIdx.x < 256) {
        const int c = threadIdx.x >> 5, w = threadIdx.x & 31;
        float v = s_red[c][w];
        #pragma unroll
        for (int o = 16; o > 0; o >>= 1)
            v += __shfl_down_sync(0xffffffffu, v, o);
        if (w == 0) out[b * CLS + c] = v + 100.0f * b2[c];
    }
}

// ---------------------------------------------------------------------------
extern "C" void kernel_launch(void* const* d_in, const int* in_sizes, int n_in,
                              void* d_out, int out_size) {
    const float* x  = (const float*)d_in[0];
    const float* W1 = (const float*)d_in[1];
    const float* b1 = (const float*)d_in[2];
    const float* W2 = (const float*)d_in[3];
    const float* b2 = (const float*)d_in[4];
    float* out = (float*)d_out;

    cudaFuncSetAttribute(gemm_fc1_mma, cudaFuncAttributeMaxDynamicSharedMemorySize,
                         SMEM_BYTES);

    convert_xw<<<X_BLOCKS + W_BLOCKS, 256>>>(x, W1);
    // grid: x = n-tiles (8) fastest -> CTAs sharing an A chunk co-scheduled
    gemm_fc1_mma<<<dim3(HID / 128, M_TOTAL / 128), 256, SMEM_BYTES>>>(b1);
    lif_reduce<<<B_SZ, 1024>>>(W2, b2, out);
}